// round 12
// baseline (speedup 1.0000x reference)
#include <cuda_runtime.h>

// HyperNetResidualV2: B=2048, D=256
// out = xin + (relu(bn2(relu(bn1(xin)) @ W1 + b1)) @ W2 + b2)
//
// R3 layout: block=128 threads handles 2 samples. Each sample is owned by a
// 64-thread group; thread q computes output elements 4q..4q+3 by a FULL-d
// dot product (256 iters, float4 weight loads). No cross-thread reduction,
// no partials smem, 2 barriers per CTA with 512 KB streamed between them.
// Double-buffered activation smem (ha -> hb) removes the anti-dependency sync.
// Grid = 1024 CTAs -> one wave on 148 SMs.
// HBM-stream bound: w1/w2 = 1.07 GB read once. Floor ~147 us @ ~7.3 TB/s.

#define DIM 256
#define BN_EPS 1e-3f

__global__ __launch_bounds__(128)
void hypernet_fused_kernel(
    const float* __restrict__ xin,
    const float* __restrict__ w1,
    const float* __restrict__ b1,
    const float* __restrict__ w2,
    const float* __restrict__ b2,
    const float* __restrict__ gamma1, const float* __restrict__ beta1,
    const float* __restrict__ mean1,  const float* __restrict__ var1,
    const float* __restrict__ gamma2, const float* __restrict__ beta2,
    const float* __restrict__ mean2,  const float* __restrict__ var2,
    float* __restrict__ out)
{
    __shared__ float ha[2][DIM];   // block-1 activations, per sample group
    __shared__ float hb[2][DIM];   // block-2 activations (double buffer)

    const int t = threadIdx.x;     // 0..127
    const int g = t >> 6;          // sample group 0/1
    const int q = t & 63;          // output quad: elements 4q..4q+3
    const int samp = blockIdx.x * 2 + g;

    const size_t vec_off = (size_t)samp * DIM + 4 * q;   // float index of this thread's quad

    // ---- BN1 + ReLU for this thread's 4 elements ----
    const float4 x0 = *reinterpret_cast<const float4*>(xin + vec_off);
    {
        const float4 gm = *reinterpret_cast<const float4*>(gamma1 + 4 * q);
        const float4 bt = *reinterpret_cast<const float4*>(beta1  + 4 * q);
        const float4 mn = *reinterpret_cast<const float4*>(mean1  + 4 * q);
        const float4 vr = *reinterpret_cast<const float4*>(var1   + 4 * q);
        float4 hv;
        hv.x = fmaxf(fmaf(x0.x - mn.x, gm.x * rsqrtf(vr.x + BN_EPS), bt.x), 0.f);
        hv.y = fmaxf(fmaf(x0.y - mn.y, gm.y * rsqrtf(vr.y + BN_EPS), bt.y), 0.f);
        hv.z = fmaxf(fmaf(x0.z - mn.z, gm.z * rsqrtf(vr.z + BN_EPS), bt.z), 0.f);
        hv.w = fmaxf(fmaf(x0.w - mn.w, gm.w * rsqrtf(vr.w + BN_EPS), bt.w), 0.f);
        *reinterpret_cast<float4*>(&ha[g][4 * q]) = hv;
    }
    __syncthreads();

    // ---- matvec 1: y[4q+j] = sum_d ha[d] * W1[samp, d, 4q+j] ----
    float4 acc1 = make_float4(0.f, 0.f, 0.f, 0.f);
    {
        const float4* __restrict__ W =
            reinterpret_cast<const float4*>(w1 + (size_t)samp * DIM * DIM) + q;
        const float* __restrict__ hrow = ha[g];
        #pragma unroll 8
        for (int d = 0; d < DIM; d++) {
            const float  hd = hrow[d];                     // warp-uniform LDS broadcast
            const float4 w  = __ldcs(&W[(size_t)d * 64]);  // LDG.128 streaming, coalesced
            acc1.x = fmaf(hd, w.x, acc1.x);
            acc1.y = fmaf(hd, w.y, acc1.y);
            acc1.z = fmaf(hd, w.z, acc1.z);
            acc1.w = fmaf(hd, w.w, acc1.w);
        }
    }

    // ---- +b1, BN2 + ReLU -> hb (different buffer, so one sync suffices) ----
    {
        const float4 bb = *reinterpret_cast<const float4*>(b1 + vec_off);
        const float4 gm = *reinterpret_cast<const float4*>(gamma2 + 4 * q);
        const float4 bt = *reinterpret_cast<const float4*>(beta2  + 4 * q);
        const float4 mn = *reinterpret_cast<const float4*>(mean2  + 4 * q);
        const float4 vr = *reinterpret_cast<const float4*>(var2   + 4 * q);
        float4 hv;
        hv.x = fmaxf(fmaf((acc1.x + bb.x) - mn.x, gm.x * rsqrtf(vr.x + BN_EPS), bt.x), 0.f);
        hv.y = fmaxf(fmaf((acc1.y + bb.y) - mn.y, gm.y * rsqrtf(vr.y + BN_EPS), bt.y), 0.f);
        hv.z = fmaxf(fmaf((acc1.z + bb.z) - mn.z, gm.z * rsqrtf(vr.z + BN_EPS), bt.z), 0.f);
        hv.w = fmaxf(fmaf((acc1.w + bb.w) - mn.w, gm.w * rsqrtf(vr.w + BN_EPS), bt.w), 0.f);
        *reinterpret_cast<float4*>(&hb[g][4 * q]) = hv;
    }
    __syncthreads();

    // ---- matvec 2 ----
    float4 acc2 = make_float4(0.f, 0.f, 0.f, 0.f);
    {
        const float4* __restrict__ W =
            reinterpret_cast<const float4*>(w2 + (size_t)samp * DIM * DIM) + q;
        const float* __restrict__ hrow = hb[g];
        #pragma unroll 8
        for (int d = 0; d < DIM; d++) {
            const float  hd = hrow[d];
            const float4 w  = __ldcs(&W[(size_t)d * 64]);
            acc2.x = fmaf(hd, w.x, acc2.x);
            acc2.y = fmaf(hd, w.y, acc2.y);
            acc2.z = fmaf(hd, w.z, acc2.z);
            acc2.w = fmaf(hd, w.w, acc2.w);
        }
    }

    // ---- +b2, residual, store (no sync needed: registers only) ----
    {
        const float4 bb = *reinterpret_cast<const float4*>(b2 + vec_off);
        float4 r;
        r.x = x0.x + acc2.x + bb.x;
        r.y = x0.y + acc2.y + bb.y;
        r.z = x0.z + acc2.z + bb.z;
        r.w = x0.w + acc2.w + bb.w;
        *reinterpret_cast<float4*>(out + vec_off) = r;
    }
}

extern "C" void kernel_launch(void* const* d_in, const int* in_sizes, int n_in,
                              void* d_out, int out_size)
{
    const float* xin    = (const float*)d_in[0];
    const float* w1     = (const float*)d_in[1];
    const float* b1     = (const float*)d_in[2];
    const float* w2     = (const float*)d_in[3];
    const float* b2     = (const float*)d_in[4];
    const float* gamma1 = (const float*)d_in[5];
    const float* beta1  = (const float*)d_in[6];
    const float* mean1  = (const float*)d_in[7];
    const float* var1   = (const float*)d_in[8];
    const float* gamma2 = (const float*)d_in[9];
    const float* beta2  = (const float*)d_in[10];
    const float* mean2  = (const float*)d_in[11];
    const float* var2   = (const float*)d_in[12];
    float* out = (float*)d_out;

    const int B = in_sizes[0] / DIM;   // 2048

    hypernet_fused_kernel<<<B / 2, 128>>>(
        xin, w1, b1, w2, b2,
        gamma1, beta1, mean1, var1,
        gamma2, beta2, mean2, var2,
        out);
}